// round 4
// baseline (speedup 1.0000x reference)
#include <cuda_runtime.h>
#include <cuda_bf16.h>
#include <cstddef>

// Problem constants
#define NB   64
#define NIC  128
#define NOC  256
#define NHW  56
#define NDG  4

// Tiling
#define OC_T 64      // output channels per block
#define SH   4       // output rows per block
#define SW   28      // output cols per block
#define ICC  8       // input-channel chunk
#define NTHREADS 224 // 8 oc-groups x 28 spatial threads

typedef unsigned long long u64;

// Premultiplied masked weights, layout [d][ic][tap][oc]  (oc contiguous)
__device__ float g_w[NDG * NIC * 9 * NOC];

// ---------------------------------------------------------------------------
// Packed f32x2 FMA (FFMA2) — 2 FMAs per instruction on sm_103a
// ---------------------------------------------------------------------------
__device__ __forceinline__ u64 ffma2(u64 a, u64 b, u64 c) {
    u64 d;
    asm("fma.rn.f32x2 %0, %1, %2, %3;" : "=l"(d) : "l"(a), "l"(b), "l"(c));
    return d;
}

// ---------------------------------------------------------------------------
// Prep: g_w[d][ic][tap][oc] = base[oc][ic][tap] * mask[d][ic][tap]
// ---------------------------------------------------------------------------
__global__ void prep_weights_kernel(const float* __restrict__ base,
                                    const float* __restrict__ mask) {
    int e = blockIdx.x * blockDim.x + threadIdx.x;
    const int total = NDG * NIC * 9 * NOC;
    if (e >= total) return;
    int oc  = e % NOC;
    int t2  = e / NOC;         // (d*128 + ic)*9 + tap
    int tap = t2 % 9;
    int t3  = t2 / 9;          // d*128 + ic
    int ic  = t3 % NIC;
    int d   = t3 / NIC;
    g_w[e] = base[(oc * NIC + ic) * 9 + tap] * mask[(d * NIC + ic) * 9 + tap];
}

// ---------------------------------------------------------------------------
// Direct tiled conv, fp32 via packed FFMA2.
// Block = (b, octile, spatial tile 4x28).
// Thread: ocg = tid%8 handles oc = ocg*8 .. ocg*8+7 (contiguous, as 4 pairs),
//         tw = tid/8 handles one w column, 4 h rows.
// Accumulators: acc[4 rows][4 oc-pairs] as packed f32x2 (32 floats).
// ---------------------------------------------------------------------------
__global__ __launch_bounds__(NTHREADS, 4)
void adaconv_kernel(const float* __restrict__ x,
                    const int*   __restrict__ label,
                    float*       __restrict__ out) {
    // x tile with value DUPLICATED in both lanes of a float2 -> one LDS.64
    // yields the broadcast operand for FFMA2 with zero register packing.
    __shared__ __align__(16) float2 xs2[ICC][SH + 2][32];   // 12 KB
    __shared__ __align__(16) float  ws[ICC][9][OC_T];       // 18 KB

    const int b      = blockIdx.z;
    const int octile = blockIdx.y;
    const int sp     = blockIdx.x;             // 0..27
    const int h0     = (sp >> 1) * SH;
    const int w0     = (sp & 1) * SW;

    const int tid = threadIdx.x;
    const int ocg = tid & 7;                   // 0..7
    const int tw  = tid >> 3;                  // 0..27

    int d = label[b];
    d = (d < 0) ? 0 : (d > NDG - 1 ? NDG - 1 : d);

    const float* __restrict__ wg = g_w + (size_t)d * NIC * 9 * NOC + octile * OC_T;
    const float* __restrict__ xg = x + (size_t)b * NIC * NHW * NHW;

    u64 acc[4][4];   // [row][oc-pair], each holds 2 packed fp32 accumulators
#pragma unroll
    for (int r = 0; r < 4; ++r)
#pragma unroll
        for (int p = 0; p < 4; ++p) acc[r][p] = 0ull;

    for (int icc = 0; icc < NIC / ICC; ++icc) {
        __syncthreads();

        // ---- load input patch: ICC x 6 x 30 (zero-padded halo), duplicated ----
        for (int idx = tid; idx < ICC * 6 * 30; idx += NTHREADS) {
            int ic  = idx / 180;
            int rem = idx % 180;
            int hh  = rem / 30;
            int ww  = rem % 30;
            int gh  = h0 - 1 + hh;
            int gw  = w0 - 1 + ww;
            float v = 0.f;
            if (gh >= 0 && gh < NHW && gw >= 0 && gw < NHW)
                v = xg[(icc * ICC + ic) * NHW * NHW + gh * NHW + gw];
            xs2[ic][hh][ww] = make_float2(v, v);
        }

        // ---- load weights: ws[ic][tap][oc], 256B-coalesced from g_w ----
        for (int idx = tid; idx < ICC * 9 * OC_T; idx += NTHREADS) {
            int oc  = idx & 63;
            int t2  = idx >> 6;
            int tap = t2 % 9;
            int ic  = t2 / 9;
            ws[ic][tap][oc] = wg[((icc * ICC + ic) * 9 + tap) * NOC + oc];
        }

        __syncthreads();

        // ---- compute: per (ic,tap): 4x LDS.64 (x pairs) + 2x LDS.128 (w) +
        //      16x FFMA2 -> fma-pipe-bound at 2 FMA/instr ----
#pragma unroll 2
        for (int ic = 0; ic < ICC; ++ic) {
#pragma unroll
            for (int kh = 0; kh < 3; ++kh) {
#pragma unroll
                for (int kw = 0; kw < 3; ++kw) {
                    // broadcast x pairs for the 4 output rows
                    u64 xv0 = *(const u64*)&xs2[ic][0 + kh][tw + kw];
                    u64 xv1 = *(const u64*)&xs2[ic][1 + kh][tw + kw];
                    u64 xv2 = *(const u64*)&xs2[ic][2 + kh][tw + kw];
                    u64 xv3 = *(const u64*)&xs2[ic][3 + kh][tw + kw];
                    // 8 contiguous weights = 4 packed pairs (2x LDS.128)
                    const float* wrow = &ws[ic][kh * 3 + kw][ocg * 8];
                    ulonglong2 wA = *(const ulonglong2*)&wrow[0];
                    ulonglong2 wB = *(const ulonglong2*)&wrow[4];

                    acc[0][0] = ffma2(xv0, wA.x, acc[0][0]);
                    acc[1][0] = ffma2(xv1, wA.x, acc[1][0]);
                    acc[2][0] = ffma2(xv2, wA.x, acc[2][0]);
                    acc[3][0] = ffma2(xv3, wA.x, acc[3][0]);

                    acc[0][1] = ffma2(xv0, wA.y, acc[0][1]);
                    acc[1][1] = ffma2(xv1, wA.y, acc[1][1]);
                    acc[2][1] = ffma2(xv2, wA.y, acc[2][1]);
                    acc[3][1] = ffma2(xv3, wA.y, acc[3][1]);

                    acc[0][2] = ffma2(xv0, wB.x, acc[0][2]);
                    acc[1][2] = ffma2(xv1, wB.x, acc[1][2]);
                    acc[2][2] = ffma2(xv2, wB.x, acc[2][2]);
                    acc[3][2] = ffma2(xv3, wB.x, acc[3][2]);

                    acc[0][3] = ffma2(xv0, wB.y, acc[0][3]);
                    acc[1][3] = ffma2(xv1, wB.y, acc[1][3]);
                    acc[2][3] = ffma2(xv2, wB.y, acc[2][3]);
                    acc[3][3] = ffma2(xv3, wB.y, acc[3][3]);
                }
            }
        }
    }

    // ---- write output: oc = octile*64 + ocg*8 + 2p (+1) ----
    float* __restrict__ og = out + ((size_t)b * NOC + octile * OC_T) * NHW * NHW
                                 + (size_t)(ocg * 8) * NHW * NHW;
#pragma unroll
    for (int p = 0; p < 4; ++p) {
#pragma unroll
        for (int r = 0; r < 4; ++r) {
            u64 v = acc[r][p];
            float lo = __uint_as_float((unsigned)(v & 0xFFFFFFFFull));
            float hi = __uint_as_float((unsigned)(v >> 32));
            size_t off = (size_t)(h0 + r) * NHW + (w0 + tw);
            og[(size_t)(2 * p)     * NHW * NHW + off] = lo;
            og[(size_t)(2 * p + 1) * NHW * NHW + off] = hi;
        }
    }
}

// ---------------------------------------------------------------------------
// Launch
// ---------------------------------------------------------------------------
extern "C" void kernel_launch(void* const* d_in, const int* in_sizes, int n_in,
                              void* d_out, int out_size) {
    const float* x     = nullptr;
    const int*   label = nullptr;
    const float* base  = nullptr;
    const float* mask  = nullptr;
    for (int i = 0; i < n_in; ++i) {
        switch (in_sizes[i]) {
            case 25690112: x     = (const float*)d_in[i]; break;
            case 64:       label = (const int*)  d_in[i]; break;
            case 294912:   base  = (const float*)d_in[i]; break;
            case 4608:     mask  = (const float*)d_in[i]; break;
            default: break; // epoch scalar etc.
        }
    }
    if (!x     && n_in > 0) x     = (const float*)d_in[0];
    if (!label && n_in > 1) label = (const int*)  d_in[1];
    if (!base  && n_in > 2) base  = (const float*)d_in[2];
    if (!mask  && n_in > 3) mask  = (const float*)d_in[3];

    float* out = (float*)d_out;

    {
        const int total = NDG * NIC * 9 * NOC;
        int threads = 256;
        int blocks  = (total + threads - 1) / threads;
        prep_weights_kernel<<<blocks, threads>>>(base, mask);
    }
    {
        dim3 grid(28, NOC / OC_T, NB);   // (spatial tiles, oc tiles, batch)
        adaconv_kernel<<<grid, NTHREADS>>>(x, label, out);
    }
}

// round 6
// speedup vs baseline: 2.3645x; 2.3645x over previous
#include <cuda_runtime.h>
#include <cuda_bf16.h>
#include <cstdint>
#include <cstddef>

#define NB   64
#define NIC  128
#define NOC  256
#define NHW  56
#define NDG  4
#define HW2  (NHW*NHW)

// ---------------- smem layout (dynamic, 120 KB) ----------------
#define SM_AH 0
#define SM_AL 32768
#define SM_BH 65536
#define SM_BL 94208
#define SMEM_TOTAL 122880

// Pre-swizzled weights: per (d, octile, tap): hi 16384 + lo 16384 bf16 elems
__device__ __align__(16) __nv_bfloat16 g_wA[NDG * 2 * 9 * 32768];

// ---------------- ptx helpers (baseline ISA only) ----------------
__device__ __forceinline__ uint32_t smem_u32(const void* p) {
    uint32_t a;
    asm("{ .reg .u64 t; cvta.to.shared.u64 t, %1; cvt.u32.u64 %0, t; }"
        : "=r"(a) : "l"(p));
    return a;
}
__device__ __forceinline__ void ldsm_x4(uint32_t* r, uint32_t addr) {
    asm volatile("ldmatrix.sync.aligned.m8n8.x4.shared.b16 {%0,%1,%2,%3}, [%4];"
                 : "=r"(r[0]), "=r"(r[1]), "=r"(r[2]), "=r"(r[3]) : "r"(addr));
}
__device__ __forceinline__ void ldsm_x2(uint32_t* r, uint32_t addr) {
    asm volatile("ldmatrix.sync.aligned.m8n8.x2.shared.b16 {%0,%1}, [%2];"
                 : "=r"(r[0]), "=r"(r[1]) : "r"(addr));
}
#define MMA_BF16(c, a, b)                                                     \
    asm volatile(                                                             \
        "mma.sync.aligned.m16n8k16.row.col.f32.bf16.bf16.f32 "                \
        "{%0,%1,%2,%3},{%4,%5,%6,%7},{%8,%9},{%0,%1,%2,%3};"                  \
        : "+f"((c)[0]), "+f"((c)[1]), "+f"((c)[2]), "+f"((c)[3])              \
        : "r"((a)[0]), "r"((a)[1]), "r"((a)[2]), "r"((a)[3]),                 \
          "r"((b)[0]), "r"((b)[1]))

// ---------------------------------------------------------------------------
// Prep: split masked weights into bf16 hi/lo, in the XOR-swizzled smem image:
// byte(oc, ic) = oc*256 + ((ic*2) ^ ((oc&7)<<4)), per 32 KB half.
// ---------------------------------------------------------------------------
__global__ void prep_weights_kernel(const float* __restrict__ base,
                                    const float* __restrict__ mask) {
    int e = blockIdx.x * blockDim.x + threadIdx.x;
    const int total = NDG * 2 * 9 * 128 * 128;
    if (e >= total) return;
    int ic  = e % 128;
    int t2  = e / 128;
    int oc  = t2 % 128;
    int t3  = t2 / 128;
    int tap = t3 % 9;
    int t4  = t3 / 9;
    int oct = t4 % 2;
    int d   = t4 / 2;

    float w = base[((size_t)(oct * 128 + oc) * 128 + ic) * 9 + tap] *
              mask[((size_t)d * 128 + ic) * 9 + tap];
    __nv_bfloat16 hi = __float2bfloat16(w);
    __nv_bfloat16 lo = __float2bfloat16(w - __bfloat162float(hi));

    uint32_t byte = (uint32_t)(oc * 256 + ((ic * 2) ^ ((oc & 7) << 4)));
    size_t slab = (size_t)((d * 2 + oct) * 9 + tap) * 32768;
    g_wA[slab + (byte >> 1)]         = hi;
    g_wA[slab + 16384 + (byte >> 1)] = lo;
}

// ---------------------------------------------------------------------------
// Main kernel: CTA = (row-pair hp, octile, b). 8 warps = 4(M) x 2(N).
// acc[2 mt][7 nt][4] fp32 per thread, accumulated over 9 taps x 8 k-steps x 3
// bf16-split passes.
// ---------------------------------------------------------------------------
__global__ __launch_bounds__(256, 1)
void adaconv_mma_kernel(const float* __restrict__ x,
                        const int*   __restrict__ label,
                        float*       __restrict__ out) {
    extern __shared__ char smem[];
    const uint32_t sb = smem_u32(smem);

    const int tid  = threadIdx.x;
    const int wid  = tid >> 5;
    const int lane = tid & 31;
    const int warp_m = wid & 3;       // 0..3  -> oc 32*warp_m
    const int warp_n = wid >> 2;      // 0..1  -> n 56*warp_n (= output row)

    const int hp  = blockIdx.x;       // 0..27 (pair of output rows)
    const int oct = blockIdx.y;       // 0..1
    const int b   = blockIdx.z;       // 0..63
    const int h0  = hp * 2;

    int d = label[b];
    d = (d < 0) ? 0 : (d > NDG - 1 ? NDG - 1 : d);

    const float* __restrict__ xg = x + (size_t)b * NIC * HW2;
    const __nv_bfloat16* __restrict__ wslab =
        g_wA + (size_t)((d * 2 + oct) * 9) * 32768;

    float acc[2][7][4];
#pragma unroll
    for (int mt = 0; mt < 2; ++mt)
#pragma unroll
        for (int nt = 0; nt < 7; ++nt)
#pragma unroll
            for (int q = 0; q < 4; ++q) acc[mt][nt][q] = 0.f;

    // per-warp ldmatrix invariants
    const int arow    = warp_m * 32 + (lane & 15);
    const uint32_t akb = (uint32_t)((lane >> 4) << 4);   // 0 or 16
    const int nbase   = warp_n * 56;

    for (int tap = 0; tap < 9; ++tap) {
        __syncthreads();   // previous tap's compute done before overwrite

        // ---- A: flat copy (pre-swizzled), 64 KB = 4096 uint4 ----
        {
            const uint4* src = (const uint4*)(wslab + (size_t)tap * 32768);
            uint4* dst = (uint4*)smem;
#pragma unroll
            for (int j = 0; j < 16; ++j) dst[tid + j * 256] = src[tid + j * 256];
        }

        // ---- B build: im2col [n=112][k=128] bf16 hi/lo, swizzled ----
        {
            const int dh = tap / 3, dw = tap % 3;
#pragma unroll 4
            for (int it = 0; it < 28; ++it) {
                int item = tid + it * 256;          // 7168 = 112 n x 64 icpair
                int n   = item % 112;
                int icp = item / 112;
                int rl  = (n >= 56) ? 1 : 0;
                int wp  = (n - rl * 56) + dw - 1;
                int hpx = h0 + rl + dh - 1;
                float v0 = 0.f, v1 = 0.f;
                if (hpx >= 0 && hpx < NHW && wp >= 0 && wp < NHW) {
                    const float* xr = xg + (size_t)(icp * 2) * HW2 + hpx * NHW + wp;
                    v0 = xr[0];
                    v1 = xr[HW2];
                }
                __nv_bfloat16 h0b = __float2bfloat16(v0);
                __nv_bfloat16 h1b = __float2bfloat16(v1);
                __nv_bfloat16 l0b = __float2bfloat16(v0 - __bfloat162float(h0b));
                __nv_bfloat16 l1b = __float2bfloat16(v1 - __bfloat162float(h1b));
                uint32_t hhw = (uint32_t)__bfloat16_as_ushort(h0b) |
                               ((uint32_t)__bfloat16_as_ushort(h1b) << 16);
                uint32_t llw = (uint32_t)__bfloat16_as_ushort(l0b) |
                               ((uint32_t)__bfloat16_as_ushort(l1b) << 16);
                uint32_t byte = (uint32_t)(n * 256 + ((icp * 4) ^ ((n & 7) << 4)));
                *(uint32_t*)(smem + SM_BH + byte) = hhw;
                *(uint32_t*)(smem + SM_BL + byte) = llw;
            }
        }
        __syncthreads();

        // ---- compute: 8 k-steps x 3 passes x 14 mma ----
#pragma unroll 1
        for (int k = 0; k < 8; ++k) {
            const uint32_t kb = (uint32_t)(k * 32) + akb;

            uint32_t ah[2][4], al[2][4];
#pragma unroll
            for (int mt = 0; mt < 2; ++mt) {
                int r = arow + mt * 16;
                uint32_t off = (uint32_t)(r * 256) + (kb ^ (uint32_t)((r & 7) << 4));
                ldsm_x4(ah[mt], sb + SM_AH + off);
                ldsm_x4(al[mt], sb + SM_AL + off);
            }

            uint32_t bh[7][2], bl[7][2];
#pragma unroll
            for (int p = 0; p < 3; ++p) {
                int n = nbase + p * 16 + (lane & 15);
                uint32_t off = (uint32_t)(n * 256) + (kb ^ (uint32_t)((n & 7) << 4));
                uint32_t t[4];
                ldsm_x4(t, sb + SM_BH + off);
                bh[2 * p][0] = t[0]; bh[2 * p][1] = t[2];
                bh[2 * p + 1][0] = t[1]; bh[2 * p + 1][1] = t[3];
                ldsm_x4(t, sb + SM_BL + off);
                bl[2 * p][0] = t[0]; bl[2 * p][1] = t[2];
                bl[2 * p + 1][0] = t[1]; bl[2 * p + 1][1] = t[3];
            }
            {   // 7th n-tile via x2
                int n = nbase + 48 + (lane & 7);
                uint32_t kb2 = (uint32_t)(k * 32) + (uint32_t)(((lane >> 3) & 1) << 4);
                uint32_t off = (uint32_t)(n * 256) + (kb2 ^ (uint32_t)((n & 7) << 4));
                uint32_t t[2];
                ldsm_x2(t, sb + SM_BH + off);
                bh[6][0] = t[0]; bh[6][1] = t[1];
                ldsm_x2(t, sb + SM_BL + off);
                bl[6][0] = t[0]; bl[6][1] = t[1];
            }

            // pass-major order: 14 independent accs between same-acc reuse
#pragma unroll
            for (int mt = 0; mt < 2; ++mt)
#pragma unroll
                for (int nt = 0; nt < 7; ++nt) MMA_BF16(acc[mt][nt], ah[mt], bh[nt]);
#pragma unroll
            for (int mt = 0; mt < 2; ++mt)
#pragma unroll
                for (int nt = 0; nt < 7; ++nt) MMA_BF16(acc[mt][nt], al[mt], bh[nt]);
#pragma unroll
            for (int mt = 0; mt < 2; ++mt)
#pragma unroll
                for (int nt = 0; nt < 7; ++nt) MMA_BF16(acc[mt][nt], ah[mt], bl[nt]);
        }
    }

    // ---- epilogue: direct stores, 32B-coalesced per row within each STG ----
    const int h = h0 + warp_n;
    const int col0 = (lane & 3) * 2;
    const int r0 = lane >> 2;
#pragma unroll
    for (int mt = 0; mt < 2; ++mt) {
        int ocb = oct * 128 + warp_m * 32 + mt * 16;
        float* __restrict__ o0 = out + ((size_t)b * NOC + ocb + r0) * HW2 + (size_t)h * NHW;
        float* __restrict__ o1 = o0 + (size_t)8 * HW2;
#pragma unroll
        for (int nt = 0; nt < 7; ++nt) {
            int w = nt * 8 + col0;
            *(float2*)(o0 + w) = make_float2(acc[mt][nt][0], acc[mt][nt][1]);
            *(float2*)(o1 + w) = make_float2(acc[mt][nt][2], acc[mt][nt][3]);
        }
    }
}

// ---------------------------------------------------------------------------
extern "C" void kernel_launch(void* const* d_in, const int* in_sizes, int n_in,
                              void* d_out, int out_size) {
    const float* x     = nullptr;
    const int*   label = nullptr;
    const float* base  = nullptr;
    const float* mask  = nullptr;
    for (int i = 0; i < n_in; ++i) {
        switch (in_sizes[i]) {
            case 25690112: x     = (const float*)d_in[i]; break;
            case 64:       label = (const int*)  d_in[i]; break;
            case 294912:   base  = (const float*)d_in[i]; break;
            case 4608:     mask  = (const float*)d_in[i]; break;
            default: break;
        }
    }
    if (!x     && n_in > 0) x     = (const float*)d_in[0];
    if (!label && n_in > 1) label = (const int*)  d_in[1];
    if (!base  && n_in > 2) base  = (const float*)d_in[2];
    if (!mask  && n_in > 3) mask  = (const float*)d_in[3];

    float* out = (float*)d_out;

    {
        const int total = NDG * 2 * 9 * 128 * 128;
        prep_weights_kernel<<<(total + 255) / 256, 256>>>(base, mask);
    }
    cudaFuncSetAttribute(adaconv_mma_kernel,
                         cudaFuncAttributeMaxDynamicSharedMemorySize, SMEM_TOTAL);
    {
        dim3 grid(28, 2, NB);
        adaconv_mma_kernel<<<grid, 256, SMEM_TOTAL>>>(x, label, out);
    }
}

// round 7
// speedup vs baseline: 3.0737x; 1.3000x over previous
#include <cuda_runtime.h>
#include <cuda_bf16.h>
#include <cstdint>
#include <cstddef>

#define NB   64
#define NIC  128
#define NOC  256
#define NHW  56
#define NDG  4
#define HW2  (NHW*NHW)

// ---------------- smem layout (dynamic, 212 KB) ----------------
// Expanded B: 232 n-rows (4 input rows x 58 w-pos) x 128 ic x bf16, hi+lo
#define SM_BH   0
#define SM_BL   59392
#define SM_AH0  118784
#define SM_AH1  151552
#define SM_AL   184320
#define SMEM_TOTAL 217088

// Pre-swizzled weights: per (d, octile, tap): hi 16384 + lo 16384 bf16 elems
__device__ __align__(16) __nv_bfloat16 g_wA[NDG * 2 * 9 * 32768];

// ---------------- ptx helpers (baseline ISA only) ----------------
__device__ __forceinline__ uint32_t smem_u32(const void* p) {
    uint32_t a;
    asm("{ .reg .u64 t; cvta.to.shared.u64 t, %1; cvt.u32.u64 %0, t; }"
        : "=r"(a) : "l"(p));
    return a;
}
__device__ __forceinline__ void ldsm_x4(uint32_t* r, uint32_t addr) {
    asm volatile("ldmatrix.sync.aligned.m8n8.x4.shared.b16 {%0,%1,%2,%3}, [%4];"
                 : "=r"(r[0]), "=r"(r[1]), "=r"(r[2]), "=r"(r[3]) : "r"(addr));
}
__device__ __forceinline__ void ldsm_x2(uint32_t* r, uint32_t addr) {
    asm volatile("ldmatrix.sync.aligned.m8n8.x2.shared.b16 {%0,%1}, [%2];"
                 : "=r"(r[0]), "=r"(r[1]) : "r"(addr));
}
__device__ __forceinline__ void cp_async16(uint32_t saddr, const void* gptr) {
    asm volatile("cp.async.cg.shared.global [%0], [%1], 16;"
                 :: "r"(saddr), "l"(gptr) : "memory");
}
#define CP_COMMIT() asm volatile("cp.async.commit_group;" ::: "memory")
#define CP_WAIT0()  asm volatile("cp.async.wait_group 0;" ::: "memory")

#define MMA_BF16(c, a, b)                                                     \
    asm volatile(                                                             \
        "mma.sync.aligned.m16n8k16.row.col.f32.bf16.bf16.f32 "                \
        "{%0,%1,%2,%3},{%4,%5,%6,%7},{%8,%9},{%0,%1,%2,%3};"                  \
        : "+f"((c)[0]), "+f"((c)[1]), "+f"((c)[2]), "+f"((c)[3])              \
        : "r"((a)[0]), "r"((a)[1]), "r"((a)[2]), "r"((a)[3]),                 \
          "r"((b)[0]), "r"((b)[1]))

// ---------------------------------------------------------------------------
// Prep: split masked weights into bf16 hi/lo, in the XOR-swizzled smem image:
// byte(oc, ic) = oc*256 + ((ic*2) ^ ((oc&7)<<4)), per 32 KB half.
// ---------------------------------------------------------------------------
__global__ void prep_weights_kernel(const float* __restrict__ base,
                                    const float* __restrict__ mask) {
    int e = blockIdx.x * blockDim.x + threadIdx.x;
    const int total = NDG * 2 * 9 * 128 * 128;
    if (e >= total) return;
    int ic  = e % 128;
    int t2  = e / 128;
    int oc  = t2 % 128;
    int t3  = t2 / 128;
    int tap = t3 % 9;
    int t4  = t3 / 9;
    int oct = t4 % 2;
    int d   = t4 / 2;

    float w = base[((size_t)(oct * 128 + oc) * 128 + ic) * 9 + tap] *
              mask[((size_t)d * 128 + ic) * 9 + tap];
    __nv_bfloat16 hi = __float2bfloat16(w);
    __nv_bfloat16 lo = __float2bfloat16(w - __bfloat162float(hi));

    uint32_t byte = (uint32_t)(oc * 256 + ((ic * 2) ^ ((oc & 7) << 4)));
    size_t slab = (size_t)((d * 2 + oct) * 9 + tap) * 32768;
    g_wA[slab + (byte >> 1)]         = hi;
    g_wA[slab + 16384 + (byte >> 1)] = lo;
}

// ---------------------------------------------------------------------------
// Main kernel: CTA = (row-pair hp, octile, b). 8 warps = 4(M) x 2(N).
// B (im2col, expanded with halos) built ONCE; 9 taps read shifted views.
// A hi double-buffered + lo single-buffered via cp.async.
// ---------------------------------------------------------------------------
__global__ __launch_bounds__(256, 1)
void adaconv_mma_kernel(const float* __restrict__ x,
                        const int*   __restrict__ label,
                        float*       __restrict__ out) {
    extern __shared__ char smem[];
    const uint32_t sb = smem_u32(smem);

    const int tid  = threadIdx.x;
    const int wid  = tid >> 5;
    const int lane = tid & 31;
    const int warp_m = wid & 3;       // oc 32*warp_m
    const int warp_n = wid >> 2;      // output row warp_n (0/1)

    const int hp  = blockIdx.x;       // 0..27
    const int oct = blockIdx.y;       // 0..1
    const int b   = blockIdx.z;       // 0..63
    const int h0  = hp * 2;

    int d = label[b];
    d = (d < 0) ? 0 : (d > NDG - 1 ? NDG - 1 : d);

    const float* __restrict__ xg = x + (size_t)b * NIC * HW2;
    const __nv_bfloat16* __restrict__ wslab =
        g_wA + (size_t)((d * 2 + oct) * 9) * 32768;

    // ---- prologue 1: issue A(0) prefetch (hi -> buf0, lo) ----
    {
        const char* gsrc = (const char*)wslab;
#pragma unroll
        for (int j = 0; j < 8; ++j) {
            cp_async16(sb + SM_AH0 + tid * 16 + j * 4096, gsrc + tid * 16 + j * 4096);
            cp_async16(sb + SM_AL  + tid * 16 + j * 4096, gsrc + 32768 + tid * 16 + j * 4096);
        }
        CP_COMMIT();
    }

    // ---- prologue 2: build expanded B once: 232 n-rows x 64 ic-pairs ----
    {
#pragma unroll 2
        for (int it = 0; it < 58; ++it) {
            int item = tid + it * 256;          // 14848 = 232 x 64
            int np  = item % 232;
            int icp = item / 232;
            int rowl = np / 58;                 // 0..3  (input row index)
            int wq   = np % 58;                 // 0..57 (w+1)
            int h_in = h0 - 1 + rowl;
            int w_in = wq - 1;
            float v0 = 0.f, v1 = 0.f;
            if (h_in >= 0 && h_in < NHW && w_in >= 0 && w_in < NHW) {
                const float* xr = xg + (size_t)(icp * 2) * HW2 + h_in * NHW + w_in;
                v0 = xr[0];
                v1 = xr[HW2];
            }
            __nv_bfloat16 h0b = __float2bfloat16(v0);
            __nv_bfloat16 h1b = __float2bfloat16(v1);
            __nv_bfloat16 l0b = __float2bfloat16(v0 - __bfloat162float(h0b));
            __nv_bfloat16 l1b = __float2bfloat16(v1 - __bfloat162float(h1b));
            uint32_t hhw = (uint32_t)__bfloat16_as_ushort(h0b) |
                           ((uint32_t)__bfloat16_as_ushort(h1b) << 16);
            uint32_t llw = (uint32_t)__bfloat16_as_ushort(l0b) |
                           ((uint32_t)__bfloat16_as_ushort(l1b) << 16);
            uint32_t byte = (uint32_t)(np * 256 + ((icp * 4) ^ ((np & 7) << 4)));
            *(uint32_t*)(smem + SM_BH + byte) = hhw;
            *(uint32_t*)(smem + SM_BL + byte) = llw;
        }
    }

    float acc[2][7][4];
#pragma unroll
    for (int mt = 0; mt < 2; ++mt)
#pragma unroll
        for (int nt = 0; nt < 7; ++nt)
#pragma unroll
            for (int q = 0; q < 4; ++q) acc[mt][nt][q] = 0.f;

    // per-warp ldmatrix invariants
    const int arow     = warp_m * 32 + (lane & 15);
    const uint32_t akb = (uint32_t)((lane >> 4) << 4);   // 0 or 16

    for (int tap = 0; tap < 9; ++tap) {
        const int dh = tap / 3, dw = tap % 3;
        const int nb = (warp_n + dh) * 58 + dw;          // expanded-B base row

        CP_WAIT0();
        __syncthreads();   // A(tap) + (tap==0: B) visible to all

        // issue next tap's A-hi into the other buffer (overlaps full tap)
        if (tap < 8) {
            const char* gsrc = (const char*)(wslab + (size_t)(tap + 1) * 32768);
            uint32_t dst = sb + ((tap & 1) ? SM_AH0 : SM_AH1);
#pragma unroll
            for (int j = 0; j < 8; ++j)
                cp_async16(dst + tid * 16 + j * 4096, gsrc + tid * 16 + j * 4096);
            CP_COMMIT();
        }

        const uint32_t ahb = sb + ((tap & 1) ? SM_AH1 : SM_AH0);
        const uint32_t alb = sb + SM_AL;

        // ---- P1: aH x bH ----
#pragma unroll 1
        for (int k = 0; k < 8; ++k) {
            const uint32_t kb = (uint32_t)(k * 32) + akb;
            uint32_t ah[2][4];
#pragma unroll
            for (int mt = 0; mt < 2; ++mt) {
                int r = arow + mt * 16;
                ldsm_x4(ah[mt], ahb + (uint32_t)(r * 256) + (kb ^ (uint32_t)((r & 7) << 4)));
            }
            uint32_t bh[7][2];
#pragma unroll
            for (int p = 0; p < 3; ++p) {
                int n = nb + p * 16 + (lane & 15);
                uint32_t t[4];
                ldsm_x4(t, sb + SM_BH + (uint32_t)(n * 256) + (kb ^ (uint32_t)((n & 7) << 4)));
                bh[2 * p][0] = t[0]; bh[2 * p][1] = t[2];
                bh[2 * p + 1][0] = t[1]; bh[2 * p + 1][1] = t[3];
            }
            {
                int n = nb + 48 + (lane & 7);
                uint32_t kb2 = (uint32_t)(k * 32) + (uint32_t)(((lane >> 3) & 1) << 4);
                uint32_t t[2];
                ldsm_x2(t, sb + SM_BH + (uint32_t)(n * 256) + (kb2 ^ (uint32_t)((n & 7) << 4)));
                bh[6][0] = t[0]; bh[6][1] = t[1];
            }
#pragma unroll
            for (int mt = 0; mt < 2; ++mt)
#pragma unroll
                for (int nt = 0; nt < 7; ++nt) MMA_BF16(acc[mt][nt], ah[mt], bh[nt]);
        }

        // ---- P2: aL x bH ----
#pragma unroll 1
        for (int k = 0; k < 8; ++k) {
            const uint32_t kb = (uint32_t)(k * 32) + akb;
            uint32_t al[2][4];
#pragma unroll
            for (int mt = 0; mt < 2; ++mt) {
                int r = arow + mt * 16;
                ldsm_x4(al[mt], alb + (uint32_t)(r * 256) + (kb ^ (uint32_t)((r & 7) << 4)));
            }
            uint32_t bh[7][2];
#pragma unroll
            for (int p = 0; p < 3; ++p) {
                int n = nb + p * 16 + (lane & 15);
                uint32_t t[4];
                ldsm_x4(t, sb + SM_BH + (uint32_t)(n * 256) + (kb ^ (uint32_t)((n & 7) << 4)));
                bh[2 * p][0] = t[0]; bh[2 * p][1] = t[2];
                bh[2 * p + 1][0] = t[1]; bh[2 * p + 1][1] = t[3];
            }
            {
                int n = nb + 48 + (lane & 7);
                uint32_t kb2 = (uint32_t)(k * 32) + (uint32_t)(((lane >> 3) & 1) << 4);
                uint32_t t[2];
                ldsm_x2(t, sb + SM_BH + (uint32_t)(n * 256) + (kb2 ^ (uint32_t)((n & 7) << 4)));
                bh[6][0] = t[0]; bh[6][1] = t[1];
            }
#pragma unroll
            for (int mt = 0; mt < 2; ++mt)
#pragma unroll
                for (int nt = 0; nt < 7; ++nt) MMA_BF16(acc[mt][nt], al[mt], bh[nt]);
        }

        __syncthreads();   // all warps done with A-lo(tap)

        // prefetch next tap's A-lo (overlaps P3)
        if (tap < 8) {
            const char* gsrc = (const char*)(wslab + (size_t)(tap + 1) * 32768) + 32768;
#pragma unroll
            for (int j = 0; j < 8; ++j)
                cp_async16(sb + SM_AL + tid * 16 + j * 4096, gsrc + tid * 16 + j * 4096);
            CP_COMMIT();
        }

        // ---- P3: aH x bL ----
#pragma unroll 1
        for (int k = 0; k < 8; ++k) {
            const uint32_t kb = (uint32_t)(k * 32) + akb;
            uint32_t ah[2][4];
#pragma unroll
            for (int mt = 0; mt < 2; ++mt) {
                int r = arow + mt * 16;
                ldsm_x4(ah[mt], ahb + (uint32_t)(r * 256) + (kb ^ (uint32_t)((r & 7) << 4)));
            }
            uint32_t bl[7][2];
#pragma unroll
            for (int p = 0; p < 3; ++p) {
                int n = nb + p * 16 + (lane & 15);
                uint32_t t[4];
                ldsm_x4(t, sb + SM_BL + (uint32_t)(n * 256) + (kb ^ (uint32_t)((n & 7) << 4)));
                bl[2 * p][0] = t[0]; bl[2 * p][1] = t[2];
                bl[2 * p + 1][0] = t[1]; bl[2 * p + 1][1] = t[3];
            }
            {
                int n = nb + 48 + (lane & 7);
                uint32_t kb2 = (uint32_t)(k * 32) + (uint32_t)(((lane >> 3) & 1) << 4);
                uint32_t t[2];
                ldsm_x2(t, sb + SM_BL + (uint32_t)(n * 256) + (kb2 ^ (uint32_t)((n & 7) << 4)));
                bl[6][0] = t[0]; bl[6][1] = t[1];
            }
#pragma unroll
            for (int mt = 0; mt < 2; ++mt)
#pragma unroll
                for (int nt = 0; nt < 7; ++nt) MMA_BF16(acc[mt][nt], ah[mt], bl[nt]);
        }
    }

    // ---- epilogue: direct stores ----
    const int h = h0 + warp_n;
    const int col0 = (lane & 3) * 2;
    const int r0 = lane >> 2;
#pragma unroll
    for (int mt = 0; mt < 2; ++mt) {
        int ocb = oct * 128 + warp_m * 32 + mt * 16;
        float* __restrict__ o0 = out + ((size_t)b * NOC + ocb + r0) * HW2 + (size_t)h * NHW;
        float* __restrict__ o1 = o0 + (size_t)8 * HW2;
#pragma unroll
        for (int nt = 0; nt < 7; ++nt) {
            int w = nt * 8 + col0;
            *(float2*)(o0 + w) = make_float2(acc[mt][nt][0], acc[mt][nt][1]);
            *(float2*)(o1 + w) = make_float2(acc[mt][nt][2], acc[mt][nt][3]);
        }
    }
}

// ---------------------------------------------------------------------------
extern "C" void kernel_launch(void* const* d_in, const int* in_sizes, int n_in,
                              void* d_out, int out_size) {
    const float* x     = nullptr;
    const int*   label = nullptr;
    const float* base  = nullptr;
    const float* mask  = nullptr;
    for (int i = 0; i < n_in; ++i) {
        switch (in_sizes[i]) {
            case 25690112: x     = (const float*)d_in[i]; break;
            case 64:       label = (const int*)  d_in[i]; break;
            case 294912:   base  = (const float*)d_in[i]; break;
            case 4608:     mask  = (const float*)d_in[i]; break;
            default: break;
        }
    }
    if (!x     && n_in > 0) x     = (const float*)d_in[0];
    if (!label && n_in > 1) label = (const int*)  d_in[1];
    if (!base  && n_in > 2) base  = (const float*)d_in[2];
    if (!mask  && n_in > 3) mask  = (const float*)d_in[3];

    float* out = (float*)d_out;

    {
        const int total = NDG * 2 * 9 * 128 * 128;
        prep_weights_kernel<<<(total + 255) / 256, 256>>>(base, mask);
    }
    cudaFuncSetAttribute(adaconv_mma_kernel,
                         cudaFuncAttributeMaxDynamicSharedMemorySize, SMEM_TOTAL);
    {
        dim3 grid(28, 2, NB);
        adaconv_mma_kernel<<<grid, 256, SMEM_TOTAL>>>(x, label, out);
    }
}

// round 8
// speedup vs baseline: 3.2040x; 1.0424x over previous
#include <cuda_runtime.h>
#include <cuda_bf16.h>
#include <cstdint>
#include <cstddef>

#define NB   64
#define NIC  128
#define NOC  256
#define NHW  56
#define NDG  4
#define HW2  (NHW*NHW)

// ---------------- smem layout (dynamic, 212 KB) ----------------
#define SM_BH   0
#define SM_BL   59392
#define SM_AH0  118784
#define SM_AH1  151552
#define SM_AL   184320
#define SMEM_TOTAL 217088

// Pre-swizzled weights: per (d, octile, tap): hi 16384 + lo 16384 bf16 elems
__device__ __align__(16) __nv_bfloat16 g_wA[NDG * 2 * 9 * 32768];

// ---------------- ptx helpers (baseline ISA only) ----------------
__device__ __forceinline__ uint32_t smem_u32(const void* p) {
    uint32_t a;
    asm("{ .reg .u64 t; cvta.to.shared.u64 t, %1; cvt.u32.u64 %0, t; }"
        : "=r"(a) : "l"(p));
    return a;
}
__device__ __forceinline__ void ldsm_x4(uint32_t* r, uint32_t addr) {
    asm volatile("ldmatrix.sync.aligned.m8n8.x4.shared.b16 {%0,%1,%2,%3}, [%4];"
                 : "=r"(r[0]), "=r"(r[1]), "=r"(r[2]), "=r"(r[3]) : "r"(addr));
}
__device__ __forceinline__ void ldsm_x2(uint32_t* r, uint32_t addr) {
    asm volatile("ldmatrix.sync.aligned.m8n8.x2.shared.b16 {%0,%1}, [%2];"
                 : "=r"(r[0]), "=r"(r[1]) : "r"(addr));
}
__device__ __forceinline__ void cp_async16(uint32_t saddr, const void* gptr) {
    asm volatile("cp.async.cg.shared.global [%0], [%1], 16;"
                 :: "r"(saddr), "l"(gptr) : "memory");
}
#define CP_COMMIT() asm volatile("cp.async.commit_group;" ::: "memory")
#define CP_WAIT0()  asm volatile("cp.async.wait_group 0;" ::: "memory")

#define MMA_BF16(c, a, b)                                                     \
    asm volatile(                                                             \
        "mma.sync.aligned.m16n8k16.row.col.f32.bf16.bf16.f32 "                \
        "{%0,%1,%2,%3},{%4,%5,%6,%7},{%8,%9},{%0,%1,%2,%3};"                  \
        : "+f"((c)[0]), "+f"((c)[1]), "+f"((c)[2]), "+f"((c)[3])              \
        : "r"((a)[0]), "r"((a)[1]), "r"((a)[2]), "r"((a)[3]),                 \
          "r"((b)[0]), "r"((b)[1]))

// ---------------------------------------------------------------------------
__global__ void prep_weights_kernel(const float* __restrict__ base,
                                    const float* __restrict__ mask) {
    int e = blockIdx.x * blockDim.x + threadIdx.x;
    const int total = NDG * 2 * 9 * 128 * 128;
    if (e >= total) return;
    int ic  = e % 128;
    int t2  = e / 128;
    int oc  = t2 % 128;
    int t3  = t2 / 128;
    int tap = t3 % 9;
    int t4  = t3 / 9;
    int oct = t4 % 2;
    int d   = t4 / 2;

    float w = base[((size_t)(oct * 128 + oc) * 128 + ic) * 9 + tap] *
              mask[((size_t)d * 128 + ic) * 9 + tap];
    __nv_bfloat16 hi = __float2bfloat16(w);
    __nv_bfloat16 lo = __float2bfloat16(w - __bfloat162float(hi));

    uint32_t byte = (uint32_t)(oc * 256 + ((ic * 2) ^ ((oc & 7) << 4)));
    size_t slab = (size_t)((d * 2 + oct) * 9 + tap) * 32768;
    g_wA[slab + (byte >> 1)]         = hi;
    g_wA[slab + 16384 + (byte >> 1)] = lo;
}

// ---------------------------------------------------------------------------
__global__ __launch_bounds__(256, 1)
void adaconv_mma_kernel(const float* __restrict__ x,
                        const int*   __restrict__ label,
                        float*       __restrict__ out) {
    extern __shared__ char smem[];
    const uint32_t sb = smem_u32(smem);

    const int tid  = threadIdx.x;
    const int wid  = tid >> 5;
    const int lane = tid & 31;
    const int warp_m = wid & 3;
    const int warp_n = wid >> 2;

    const int hp  = blockIdx.x;
    const int oct = blockIdx.y;
    const int b   = blockIdx.z;
    const int h0  = hp * 2;

    int d = label[b];
    d = (d < 0) ? 0 : (d > NDG - 1 ? NDG - 1 : d);

    const float* __restrict__ xg = x + (size_t)b * NIC * HW2;
    const char* __restrict__ wbase =
        (const char*)(g_wA + (size_t)((d * 2 + oct) * 9) * 32768);

    // ---- prologue: A(0) hi+lo prefetch ----
    {
#pragma unroll
        for (int j = 0; j < 8; ++j) {
            cp_async16(sb + SM_AH0 + tid * 16 + j * 4096, wbase + tid * 16 + j * 4096);
            cp_async16(sb + SM_AL  + tid * 16 + j * 4096, wbase + 32768 + tid * 16 + j * 4096);
        }
        CP_COMMIT();
    }

    // ---- build expanded B once ----
    {
#pragma unroll 2
        for (int it = 0; it < 58; ++it) {
            int item = tid + it * 256;
            int np  = item % 232;
            int icp = item / 232;
            int rowl = np / 58;
            int wq   = np % 58;
            int h_in = h0 - 1 + rowl;
            int w_in = wq - 1;
            float v0 = 0.f, v1 = 0.f;
            if (h_in >= 0 && h_in < NHW && w_in >= 0 && w_in < NHW) {
                const float* xr = xg + (size_t)(icp * 2) * HW2 + h_in * NHW + w_in;
                v0 = xr[0];
                v1 = xr[HW2];
            }
            __nv_bfloat16 h0b = __float2bfloat16(v0);
            __nv_bfloat16 h1b = __float2bfloat16(v1);
            __nv_bfloat16 l0b = __float2bfloat16(v0 - __bfloat162float(h0b));
            __nv_bfloat16 l1b = __float2bfloat16(v1 - __bfloat162float(h1b));
            uint32_t hhw = (uint32_t)__bfloat16_as_ushort(h0b) |
                           ((uint32_t)__bfloat16_as_ushort(h1b) << 16);
            uint32_t llw = (uint32_t)__bfloat16_as_ushort(l0b) |
                           ((uint32_t)__bfloat16_as_ushort(l1b) << 16);
            uint32_t byte = (uint32_t)(np * 256 + ((icp * 4) ^ ((np & 7) << 4)));
            *(uint32_t*)(smem + SM_BH + byte) = hhw;
            *(uint32_t*)(smem + SM_BL + byte) = llw;
        }
    }

    float acc[2][7][4];
#pragma unroll
    for (int mt = 0; mt < 2; ++mt)
#pragma unroll
        for (int nt = 0; nt < 7; ++nt)
#pragma unroll
            for (int q = 0; q < 4; ++q) acc[mt][nt][q] = 0.f;

    const int arow     = warp_m * 32 + (lane & 15);
    const uint32_t akb = (uint32_t)((lane >> 4) << 4);

    // fragment double buffers
    uint32_t ah[2][2][4], al[2][2][4], bh[2][7][2], bl[2][7][2];

    for (int tap = 0; tap < 9; ++tap) {
        const int dh = tap / 3, dw = tap % 3;
        const int nb = (warp_n + dh) * 58 + dw;
        const uint32_t ahb = sb + ((tap & 1) ? SM_AH1 : SM_AH0);
        const uint32_t alb = sb + SM_AL;

        CP_WAIT0();
        __syncthreads();   // A(tap) hi + ALh0/h1 visible; safe to overwrite dead bufs

        // issue AH(tap+1) -> alt buffer; ALh1(tap) for tap>=1 (prologue covered tap 0)
        {
            if (tap < 8) {
                const char* gsrc = wbase + (size_t)(tap + 1) * 65536;
                uint32_t dst = sb + ((tap & 1) ? SM_AH0 : SM_AH1);
#pragma unroll
                for (int j = 0; j < 8; ++j)
                    cp_async16(dst + tid * 16 + j * 4096, gsrc + tid * 16 + j * 4096);
            }
            if (tap >= 1) {
                const char* gsrc = wbase + (size_t)tap * 65536 + 32768;   // lo slab
#pragma unroll
                for (int j = 0; j < 4; ++j) {   // half1: bytes 128..255 of each row
                    int c = tid + j * 256;      // 1024 chunks
                    uint32_t off = (uint32_t)((c >> 3) * 256 + 128 + (c & 7) * 16);
                    cp_async16(sb + SM_AL + off, gsrc + off);
                }
            }
            CP_COMMIT();
        }

        // ---- fragment loader ----
        auto load_frags = [&](int k, int s) {
            const uint32_t kb = (uint32_t)(k * 32) + akb;
#pragma unroll
            for (int mt = 0; mt < 2; ++mt) {
                int r = arow + mt * 16;
                uint32_t off = (uint32_t)(r * 256) + (kb ^ (uint32_t)((r & 7) << 4));
                ldsm_x4(ah[s][mt], ahb + off);
                ldsm_x4(al[s][mt], alb + off);
            }
#pragma unroll
            for (int p = 0; p < 3; ++p) {
                int n = nb + p * 16 + (lane & 15);
                uint32_t off = (uint32_t)(n * 256) + (kb ^ (uint32_t)((n & 7) << 4));
                uint32_t t[4];
                ldsm_x4(t, sb + SM_BH + off);
                bh[s][2 * p][0] = t[0]; bh[s][2 * p][1] = t[2];
                bh[s][2 * p + 1][0] = t[1]; bh[s][2 * p + 1][1] = t[3];
                ldsm_x4(t, sb + SM_BL + off);
                bl[s][2 * p][0] = t[0]; bl[s][2 * p][1] = t[2];
                bl[s][2 * p + 1][0] = t[1]; bl[s][2 * p + 1][1] = t[3];
            }
            {
                int n = nb + 48 + (lane & 7);
                uint32_t kb2 = (uint32_t)(k * 32) + (uint32_t)(((lane >> 3) & 1) << 4);
                uint32_t off = (uint32_t)(n * 256) + (kb2 ^ (uint32_t)((n & 7) << 4));
                uint32_t t[2];
                ldsm_x2(t, sb + SM_BH + off);
                bh[s][6][0] = t[0]; bh[s][6][1] = t[1];
                ldsm_x2(t, sb + SM_BL + off);
                bl[s][6][0] = t[0]; bl[s][6][1] = t[1];
            }
        };
        auto mma_block = [&](int s) {
#pragma unroll
            for (int mt = 0; mt < 2; ++mt)
#pragma unroll
                for (int nt = 0; nt < 7; ++nt) MMA_BF16(acc[mt][nt], ah[s][mt], bh[s][nt]);
#pragma unroll
            for (int mt = 0; mt < 2; ++mt)
#pragma unroll
                for (int nt = 0; nt < 7; ++nt) MMA_BF16(acc[mt][nt], al[s][mt], bh[s][nt]);
#pragma unroll
            for (int mt = 0; mt < 2; ++mt)
#pragma unroll
                for (int nt = 0; nt < 7; ++nt) MMA_BF16(acc[mt][nt], ah[s][mt], bl[s][nt]);
        };

        // ---- k = 0..3 (AL half0), 2-deep pipelined ----
        load_frags(0, 0);
#pragma unroll
        for (int k = 0; k < 4; ++k) {
            if (k < 3) load_frags(k + 1, (k + 1) & 1);
            mma_block(k & 1);
        }

        // ---- mid-tap: recycle ALh0, ensure ALh1(tap) arrived ----
        CP_WAIT0();        // waits AH(tap+1) + ALh1(tap) (covered by k0-3)
        __syncthreads();   // all warps done reading ALh0(tap); cp data visible
        if (tap < 8) {
            const char* gsrc = wbase + (size_t)(tap + 1) * 65536 + 32768;
#pragma unroll
            for (int j = 0; j < 4; ++j) {       // half0 of next tap's lo
                int c = tid + j * 256;
                uint32_t off = (uint32_t)((c >> 3) * 256 + (c & 7) * 16);
                cp_async16(sb + SM_AL + off, gsrc + off);
            }
            CP_COMMIT();
        }

        // ---- k = 4..7 (AL half1), pipelined ----
        load_frags(4, 0);
#pragma unroll
        for (int k = 4; k < 8; ++k) {
            if (k < 7) load_frags(k + 1, (k + 1) & 1);
            mma_block(k & 1);
        }
    }

    // ---- epilogue ----
    const int h = h0 + warp_n;
    const int col0 = (lane & 3) * 2;
    const int r0 = lane >> 2;
#pragma unroll
    for (int mt = 0; mt < 2; ++mt) {
        int ocb = oct * 128 + warp_m * 32 + mt * 16;
        float* __restrict__ o0 = out + ((size_t)b * NOC + ocb + r0) * HW2 + (size_t)h * NHW;
        float* __restrict__ o1 = o0 + (size_t)8 * HW2;
#pragma unroll
        for (int nt = 0; nt < 7; ++nt) {
            int w = nt * 8 + col0;
            *(float2*)(o0 + w) = make_float2(acc[mt][nt][0], acc[mt][nt][1]);
            *(float2*)(o1 + w) = make_float2(acc[mt][nt][2], acc[mt][nt][3]);
        }
    }
}

// ---------------------------------------------------------------------------
extern "C" void kernel_launch(void* const* d_in, const int* in_sizes, int n_in,
                              void* d_out, int out_size) {
    const float* x     = nullptr;
    const int*   label = nullptr;
    const float* base  = nullptr;
    const float* mask  = nullptr;
    for (int i = 0; i < n_in; ++i) {
        switch (in_sizes[i]) {
            case 25690112: x     = (const float*)d_in[i]; break;
            case 64:       label = (const int*)  d_in[i]; break;
            case 294912:   base  = (const float*)d_in[i]; break;
            case 4608:     mask  = (const float*)d_in[i]; break;
            default: break;
        }
    }
    if (!x     && n_in > 0) x     = (const float*)d_in[0];
    if (!label && n_in > 1) label = (const int*)  d_in[1];
    if (!base  && n_in > 2) base  = (const float*)d_in[2];
    if (!mask  && n_in > 3) mask  = (const float*)d_in[3];

    float* out = (float*)d_out;

    {
        const int total = NDG * 2 * 9 * 128 * 128;
        prep_weights_kernel<<<(total + 255) / 256, 256>>>(base, mask);
    }
    cudaFuncSetAttribute(adaconv_mma_kernel,
                         cudaFuncAttributeMaxDynamicSharedMemorySize, SMEM_TOTAL);
    {
        dim3 grid(28, 2, NB);
        adaconv_mma_kernel<<<grid, 256, SMEM_TOTAL>>>(x, label, out);
    }
}

// round 9
// speedup vs baseline: 3.3690x; 1.0515x over previous
#include <cuda_runtime.h>
#include <cuda_bf16.h>
#include <cstdint>
#include <cstddef>

#define NB   64
#define NIC  128
#define NOC  256
#define NHW  56
#define NDG  4
#define HW2  (NHW*NHW)

#define NTHREADS 512

// ---------------- smem layout (dynamic, 212 KB) ----------------
#define SM_BH   0
#define SM_BL   59392
#define SM_AH0  118784
#define SM_AH1  151552
#define SM_AL   184320
#define SMEM_TOTAL 217088

// Pre-swizzled weights: per (d, octile, tap): hi 16384 + lo 16384 bf16 elems
__device__ __align__(16) __nv_bfloat16 g_wA[NDG * 2 * 9 * 32768];

// ---------------- ptx helpers (baseline ISA only) ----------------
__device__ __forceinline__ uint32_t smem_u32(const void* p) {
    uint32_t a;
    asm("{ .reg .u64 t; cvta.to.shared.u64 t, %1; cvt.u32.u64 %0, t; }"
        : "=r"(a) : "l"(p));
    return a;
}
__device__ __forceinline__ void ldsm_x4(uint32_t* r, uint32_t addr) {
    asm volatile("ldmatrix.sync.aligned.m8n8.x4.shared.b16 {%0,%1,%2,%3}, [%4];"
                 : "=r"(r[0]), "=r"(r[1]), "=r"(r[2]), "=r"(r[3]) : "r"(addr));
}
__device__ __forceinline__ void ldsm_x2(uint32_t* r, uint32_t addr) {
    asm volatile("ldmatrix.sync.aligned.m8n8.x2.shared.b16 {%0,%1}, [%2];"
                 : "=r"(r[0]), "=r"(r[1]) : "r"(addr));
}
__device__ __forceinline__ void cp_async16(uint32_t saddr, const void* gptr) {
    asm volatile("cp.async.cg.shared.global [%0], [%1], 16;"
                 :: "r"(saddr), "l"(gptr) : "memory");
}
#define CP_COMMIT() asm volatile("cp.async.commit_group;" ::: "memory")
#define CP_WAIT0()  asm volatile("cp.async.wait_group 0;" ::: "memory")

#define MMA_BF16(c, a, b)                                                     \
    asm volatile(                                                             \
        "mma.sync.aligned.m16n8k16.row.col.f32.bf16.bf16.f32 "                \
        "{%0,%1,%2,%3},{%4,%5,%6,%7},{%8,%9},{%0,%1,%2,%3};"                  \
        : "+f"((c)[0]), "+f"((c)[1]), "+f"((c)[2]), "+f"((c)[3])              \
        : "r"((a)[0]), "r"((a)[1]), "r"((a)[2]), "r"((a)[3]),                 \
          "r"((b)[0]), "r"((b)[1]))

// ---------------------------------------------------------------------------
__global__ void prep_weights_kernel(const float* __restrict__ base,
                                    const float* __restrict__ mask) {
    int e = blockIdx.x * blockDim.x + threadIdx.x;
    const int total = NDG * 2 * 9 * 128 * 128;
    if (e >= total) return;
    int ic  = e % 128;
    int t2  = e / 128;
    int oc  = t2 % 128;
    int t3  = t2 / 128;
    int tap = t3 % 9;
    int t4  = t3 / 9;
    int oct = t4 % 2;
    int d   = t4 / 2;

    float w = base[((size_t)(oct * 128 + oc) * 128 + ic) * 9 + tap] *
              mask[((size_t)d * 128 + ic) * 9 + tap];
    __nv_bfloat16 hi = __float2bfloat16(w);
    __nv_bfloat16 lo = __float2bfloat16(w - __bfloat162float(hi));

    uint32_t byte = (uint32_t)(oc * 256 + ((ic * 2) ^ ((oc & 7) << 4)));
    size_t slab = (size_t)((d * 2 + oct) * 9 + tap) * 32768;
    g_wA[slab + (byte >> 1)]         = hi;
    g_wA[slab + 16384 + (byte >> 1)] = lo;
}

// ---------------------------------------------------------------------------
// CTA = (row-pair hp, octile, b), 512 threads = 16 warps: 8 M-warps (16 oc)
// x 2 N-warps (1 output row). acc[7][4] per thread.
// ---------------------------------------------------------------------------
__global__ __launch_bounds__(NTHREADS, 1)
void adaconv_mma_kernel(const float* __restrict__ x,
                        const int*   __restrict__ label,
                        float*       __restrict__ out) {
    extern __shared__ char smem[];
    const uint32_t sb = smem_u32(smem);

    const int tid  = threadIdx.x;
    const int wid  = tid >> 5;
    const int lane = tid & 31;
    const int warp_m = wid & 7;       // oc tile of 16
    const int warp_n = wid >> 3;      // output row (0/1)

    const int hp  = blockIdx.x;
    const int oct = blockIdx.y;
    const int b   = blockIdx.z;
    const int h0  = hp * 2;

    int d = label[b];
    d = (d < 0) ? 0 : (d > NDG - 1 ? NDG - 1 : d);

    const float* __restrict__ xg = x + (size_t)b * NIC * HW2;
    const char* __restrict__ wbase =
        (const char*)(g_wA + (size_t)((d * 2 + oct) * 9) * 32768);

    // ---- prologue: A(0) hi+lo prefetch (2048 chunks each, 512 threads) ----
    {
#pragma unroll
        for (int j = 0; j < 4; ++j) {
            cp_async16(sb + SM_AH0 + tid * 16 + j * 8192, wbase + tid * 16 + j * 8192);
            cp_async16(sb + SM_AL  + tid * 16 + j * 8192, wbase + 32768 + tid * 16 + j * 8192);
        }
        CP_COMMIT();
    }

    // ---- build expanded B once: 14848 items = 232 n x 64 ic-pairs ----
    {
#pragma unroll 2
        for (int it = 0; it < 29; ++it) {
            int item = tid + it * NTHREADS;
            int np  = item % 232;
            int icp = item / 232;
            int rowl = np / 58;
            int wq   = np % 58;
            int h_in = h0 - 1 + rowl;
            int w_in = wq - 1;
            float v0 = 0.f, v1 = 0.f;
            if (h_in >= 0 && h_in < NHW && w_in >= 0 && w_in < NHW) {
                const float* xr = xg + (size_t)(icp * 2) * HW2 + h_in * NHW + w_in;
                v0 = xr[0];
                v1 = xr[HW2];
            }
            __nv_bfloat16 h0b = __float2bfloat16(v0);
            __nv_bfloat16 h1b = __float2bfloat16(v1);
            __nv_bfloat16 l0b = __float2bfloat16(v0 - __bfloat162float(h0b));
            __nv_bfloat16 l1b = __float2bfloat16(v1 - __bfloat162float(h1b));
            uint32_t hhw = (uint32_t)__bfloat16_as_ushort(h0b) |
                           ((uint32_t)__bfloat16_as_ushort(h1b) << 16);
            uint32_t llw = (uint32_t)__bfloat16_as_ushort(l0b) |
                           ((uint32_t)__bfloat16_as_ushort(l1b) << 16);
            uint32_t byte = (uint32_t)(np * 256 + ((icp * 4) ^ ((np & 7) << 4)));
            *(uint32_t*)(smem + SM_BH + byte) = hhw;
            *(uint32_t*)(smem + SM_BL + byte) = llw;
        }
    }

    float acc[7][4];
#pragma unroll
    for (int nt = 0; nt < 7; ++nt)
#pragma unroll
        for (int q = 0; q < 4; ++q) acc[nt][q] = 0.f;

    const int arow     = warp_m * 16 + (lane & 15);
    const uint32_t akb = (uint32_t)((lane >> 4) << 4);

    // fragment double buffers
    uint32_t ah[2][4], al[2][4], bh[2][7][2], bl[2][7][2];

    for (int tap = 0; tap < 9; ++tap) {
        const int dh = tap / 3, dw = tap % 3;
        const int nb = (warp_n + dh) * 58 + dw;
        const uint32_t ahb = sb + ((tap & 1) ? SM_AH1 : SM_AH0);
        const uint32_t alb = sb + SM_AL;

        CP_WAIT0();
        __syncthreads();

        // issue AH(tap+1) -> alt buffer; ALh1(tap) for tap>=1
        {
            if (tap < 8) {
                const char* gsrc = wbase + (size_t)(tap + 1) * 65536;
                uint32_t dst = sb + ((tap & 1) ? SM_AH0 : SM_AH1);
#pragma unroll
                for (int j = 0; j < 4; ++j)
                    cp_async16(dst + tid * 16 + j * 8192, gsrc + tid * 16 + j * 8192);
            }
            if (tap >= 1) {
                const char* gsrc = wbase + (size_t)tap * 65536 + 32768;
#pragma unroll
                for (int j = 0; j < 2; ++j) {   // half1: bytes 128..255 of each row
                    int c = tid + j * NTHREADS; // 1024 chunks
                    uint32_t off = (uint32_t)((c >> 3) * 256 + 128 + (c & 7) * 16);
                    cp_async16(sb + SM_AL + off, gsrc + off);
                }
            }
            CP_COMMIT();
        }

        auto load_frags = [&](int k, int s) {
            const uint32_t kb = (uint32_t)(k * 32) + akb;
            {
                uint32_t off = (uint32_t)(arow * 256) + (kb ^ (uint32_t)((arow & 7) << 4));
                ldsm_x4(ah[s], ahb + off);
                ldsm_x4(al[s], alb + off);
            }
#pragma unroll
            for (int p = 0; p < 3; ++p) {
                int n = nb + p * 16 + (lane & 15);
                uint32_t off = (uint32_t)(n * 256) + (kb ^ (uint32_t)((n & 7) << 4));
                uint32_t t[4];
                ldsm_x4(t, sb + SM_BH + off);
                bh[s][2 * p][0] = t[0]; bh[s][2 * p][1] = t[2];
                bh[s][2 * p + 1][0] = t[1]; bh[s][2 * p + 1][1] = t[3];
                ldsm_x4(t, sb + SM_BL + off);
                bl[s][2 * p][0] = t[0]; bl[s][2 * p][1] = t[2];
                bl[s][2 * p + 1][0] = t[1]; bl[s][2 * p + 1][1] = t[3];
            }
            {
                int n = nb + 48 + (lane & 7);
                uint32_t kb2 = (uint32_t)(k * 32) + (uint32_t)(((lane >> 3) & 1) << 4);
                uint32_t off = (uint32_t)(n * 256) + (kb2 ^ (uint32_t)((n & 7) << 4));
                uint32_t t[2];
                ldsm_x2(t, sb + SM_BH + off);
                bh[s][6][0] = t[0]; bh[s][6][1] = t[1];
                ldsm_x2(t, sb + SM_BL + off);
                bl[s][6][0] = t[0]; bl[s][6][1] = t[1];
            }
        };
        auto mma_block = [&](int s) {
#pragma unroll
            for (int nt = 0; nt < 7; ++nt) MMA_BF16(acc[nt], ah[s], bh[s][nt]);
#pragma unroll
            for (int nt = 0; nt < 7; ++nt) MMA_BF16(acc[nt], al[s], bh[s][nt]);
#pragma unroll
            for (int nt = 0; nt < 7; ++nt) MMA_BF16(acc[nt], ah[s], bl[s][nt]);
        };

        // ---- k = 0..3 (AL half0), 2-deep pipelined ----
        load_frags(0, 0);
#pragma unroll
        for (int k = 0; k < 4; ++k) {
            if (k < 3) load_frags(k + 1, (k + 1) & 1);
            mma_block(k & 1);
        }

        // ---- mid-tap: recycle ALh0 ----
        CP_WAIT0();
        __syncthreads();
        if (tap < 8) {
            const char* gsrc = wbase + (size_t)(tap + 1) * 65536 + 32768;
#pragma unroll
            for (int j = 0; j < 2; ++j) {       // half0 of next tap's lo
                int c = tid + j * NTHREADS;
                uint32_t off = (uint32_t)((c >> 3) * 256 + (c & 7) * 16);
                cp_async16(sb + SM_AL + off, gsrc + off);
            }
            CP_COMMIT();
        }

        // ---- k = 4..7 (AL half1), pipelined ----
        load_frags(4, 0);
#pragma unroll
        for (int k = 4; k < 8; ++k) {
            if (k < 7) load_frags(k + 1, (k + 1) & 1);
            mma_block(k & 1);
        }
    }

    // ---- epilogue ----
    const int h = h0 + warp_n;
    const int col0 = (lane & 3) * 2;
    const int r0 = lane >> 2;
    {
        int ocb = oct * 128 + warp_m * 16;
        float* __restrict__ o0 = out + ((size_t)b * NOC + ocb + r0) * HW2 + (size_t)h * NHW;
        float* __restrict__ o1 = o0 + (size_t)8 * HW2;
#pragma unroll
        for (int nt = 0; nt < 7; ++nt) {
            int w = nt * 8 + col0;
            *(float2*)(o0 + w) = make_float2(acc[nt][0], acc[nt][1]);
            *(float2*)(o1 + w) = make_float2(acc[nt][2], acc[nt][3]);
        }
    }
}

// ---------------------------------------------------------------------------
extern "C" void kernel_launch(void* const* d_in, const int* in_sizes, int n_in,
                              void* d_out, int out_size) {
    const float* x     = nullptr;
    const int*   label = nullptr;
    const float* base  = nullptr;
    const float* mask  = nullptr;
    for (int i = 0; i < n_in; ++i) {
        switch (in_sizes[i]) {
            case 25690112: x     = (const float*)d_in[i]; break;
            case 64:       label = (const int*)  d_in[i]; break;
            case 294912:   base  = (const float*)d_in[i]; break;
            case 4608:     mask  = (const float*)d_in[i]; break;
            default: break;
        }
    }
    if (!x     && n_in > 0) x     = (const float*)d_in[0];
    if (!label && n_in > 1) label = (const int*)  d_in[1];
    if (!base  && n_in > 2) base  = (const float*)d_in[2];
    if (!mask  && n_in > 3) mask  = (const float*)d_in[3];

    float* out = (float*)d_out;

    {
        const int total = NDG * 2 * 9 * 128 * 128;
        prep_weights_kernel<<<(total + 255) / 256, 256>>>(base, mask);
    }
    cudaFuncSetAttribute(adaconv_mma_kernel,
                         cudaFuncAttributeMaxDynamicSharedMemorySize, SMEM_TOTAL);
    {
        dim3 grid(28, 2, NB);
        adaconv_mma_kernel<<<grid, NTHREADS, SMEM_TOTAL>>>(x, label, out);
    }
}

// round 10
// speedup vs baseline: 6.8761x; 2.0410x over previous
#include <cuda_runtime.h>
#include <cuda_fp16.h>
#include <cstdint>
#include <cstddef>

#define NB   64
#define NIC  128
#define NOC  256
#define NHW  56
#define NDG  4
#define HW2  (NHW*NHW)

#define NTHREADS 512
#define ROWS_PER_CTA 4
#define BROWS 348                  // (4+2 halo rows) x 58 w-positions

// ---------------- smem layout (dynamic, 151 KB) ----------------
#define SM_BH   0                  // 348 * 256 B = 89088
#define SM_AH0  89088              // 32 KB
#define SM_AH1  121856             // 32 KB
#define SMEM_TOTAL 154624

// Pre-swizzled fp16 weights: per (d, octile, tap): 16384 halfs (32 KB)
__device__ __align__(16) __half g_w2[NDG * 2 * 9 * 16384];

// ---------------- ptx helpers (baseline ISA only) ----------------
__device__ __forceinline__ uint32_t smem_u32(const void* p) {
    uint32_t a;
    asm("{ .reg .u64 t; cvta.to.shared.u64 t, %1; cvt.u32.u64 %0, t; }"
        : "=r"(a) : "l"(p));
    return a;
}
__device__ __forceinline__ void ldsm_x4(uint32_t* r, uint32_t addr) {
    asm volatile("ldmatrix.sync.aligned.m8n8.x4.shared.b16 {%0,%1,%2,%3}, [%4];"
                 : "=r"(r[0]), "=r"(r[1]), "=r"(r[2]), "=r"(r[3]) : "r"(addr));
}
__device__ __forceinline__ void ldsm_x2(uint32_t* r, uint32_t addr) {
    asm volatile("ldmatrix.sync.aligned.m8n8.x2.shared.b16 {%0,%1}, [%2];"
                 : "=r"(r[0]), "=r"(r[1]) : "r"(addr));
}
__device__ __forceinline__ void cp_async16(uint32_t saddr, const void* gptr) {
    asm volatile("cp.async.cg.shared.global [%0], [%1], 16;"
                 :: "r"(saddr), "l"(gptr) : "memory");
}
#define CP_COMMIT() asm volatile("cp.async.commit_group;" ::: "memory")
#define CP_WAIT0()  asm volatile("cp.async.wait_group 0;" ::: "memory")

#define MMA_FP16(c, a, b)                                                     \
    asm volatile(                                                             \
        "mma.sync.aligned.m16n8k16.row.col.f32.f16.f16.f32 "                  \
        "{%0,%1,%2,%3},{%4,%5,%6,%7},{%8,%9},{%0,%1,%2,%3};"                  \
        : "+f"((c)[0]), "+f"((c)[1]), "+f"((c)[2]), "+f"((c)[3])              \
        : "r"((a)[0]), "r"((a)[1]), "r"((a)[2]), "r"((a)[3]),                 \
          "r"((b)[0]), "r"((b)[1]))

// ---------------------------------------------------------------------------
// Prep: masked weights -> fp16, XOR-swizzled smem image
// byte(oc, ic) = oc*256 + ((ic*2) ^ ((oc&7)<<4))
// ---------------------------------------------------------------------------
__global__ void prep_weights_kernel(const float* __restrict__ base,
                                    const float* __restrict__ mask) {
    int e = blockIdx.x * blockDim.x + threadIdx.x;
    const int total = NDG * 2 * 9 * 128 * 128;
    if (e >= total) return;
    int ic  = e % 128;
    int t2  = e / 128;
    int oc  = t2 % 128;
    int t3  = t2 / 128;
    int tap = t3 % 9;
    int t4  = t3 / 9;
    int oct = t4 % 2;
    int d   = t4 / 2;

    float w = base[((size_t)(oct * 128 + oc) * 128 + ic) * 9 + tap] *
              mask[((size_t)d * 128 + ic) * 9 + tap];

    uint32_t byte = (uint32_t)(oc * 256 + ((ic * 2) ^ ((oc & 7) << 4)));
    size_t slab = (size_t)((d * 2 + oct) * 9 + tap) * 16384;
    g_w2[slab + (byte >> 1)] = __float2half(w);
}

// ---------------------------------------------------------------------------
// CTA = (4-row block, octile 128, b). 16 warps = 4 M-warps (32 oc) x
// 4 N-warps (1 output row, N=56). Single-pass fp16, fp32 accum.
// ---------------------------------------------------------------------------
__global__ __launch_bounds__(NTHREADS, 1)
void adaconv_mma_kernel(const float* __restrict__ x,
                        const int*   __restrict__ label,
                        float*       __restrict__ out) {
    extern __shared__ char smem[];
    const uint32_t sb = smem_u32(smem);

    const int tid  = threadIdx.x;
    const int wid  = tid >> 5;
    const int lane = tid & 31;
    const int warp_m = wid & 3;       // oc tile of 32
    const int warp_n = wid >> 2;      // output row (0..3)

    const int hb  = blockIdx.x;       // 0..13
    const int oct = blockIdx.y;       // 0..1
    const int b   = blockIdx.z;       // 0..63
    const int h0  = hb * ROWS_PER_CTA;

    int d = label[b];
    d = (d < 0) ? 0 : (d > NDG - 1 ? NDG - 1 : d);

    const float* __restrict__ xg = x + (size_t)b * NIC * HW2;
    const char* __restrict__ wbase =
        (const char*)(g_w2 + (size_t)((d * 2 + oct) * 9) * 16384);

    // ---- prologue: A(0) prefetch (2048 x 16B) ----
    {
#pragma unroll
        for (int j = 0; j < 4; ++j)
            cp_async16(sb + SM_AH0 + tid * 16 + j * 8192, wbase + tid * 16 + j * 8192);
        CP_COMMIT();
    }

    // ---- build expanded B once: 348 n-rows x 64 ic-pairs = 22272 items ----
    {
#pragma unroll 2
        for (int it = 0; it < 44; ++it) {
            int item = tid + it * NTHREADS;
            if (item < BROWS * 64) {
                int np  = item % BROWS;
                int icp = item / BROWS;
                int rowl = np / 58;           // 0..5 (input row)
                int wq   = np % 58;
                int h_in = h0 - 1 + rowl;
                int w_in = wq - 1;
                float v0 = 0.f, v1 = 0.f;
                if (h_in >= 0 && h_in < NHW && w_in >= 0 && w_in < NHW) {
                    const float* xr = xg + (size_t)(icp * 2) * HW2 + h_in * NHW + w_in;
                    v0 = xr[0];
                    v1 = xr[HW2];
                }
                __half h0b = __float2half(v0);
                __half h1b = __float2half(v1);
                uint32_t hw = (uint32_t)__half_as_ushort(h0b) |
                              ((uint32_t)__half_as_ushort(h1b) << 16);
                uint32_t byte = (uint32_t)(np * 256 + ((icp * 4) ^ ((np & 7) << 4)));
                *(uint32_t*)(smem + SM_BH + byte) = hw;
            }
        }
    }

    float acc[2][7][4];
#pragma unroll
    for (int mt = 0; mt < 2; ++mt)
#pragma unroll
        for (int nt = 0; nt < 7; ++nt)
#pragma unroll
            for (int q = 0; q < 4; ++q) acc[mt][nt][q] = 0.f;

    const int arow     = warp_m * 32 + (lane & 15);
    const uint32_t akb = (uint32_t)((lane >> 4) << 4);

    // fragment double buffers
    uint32_t ah[2][2][4], bh[2][7][2];

    for (int tap = 0; tap < 9; ++tap) {
        const int dh = tap / 3, dw = tap % 3;
        const int nb = (warp_n + dh) * 58 + dw;
        const uint32_t ahb = sb + ((tap & 1) ? SM_AH1 : SM_AH0);

        CP_WAIT0();
        __syncthreads();   // A(tap) + (tap==0: B) visible; alt buffer reads done

        if (tap < 8) {
            const char* gsrc = wbase + (size_t)(tap + 1) * 32768;
            uint32_t dst = sb + ((tap & 1) ? SM_AH0 : SM_AH1);
#pragma unroll
            for (int j = 0; j < 4; ++j)
                cp_async16(dst + tid * 16 + j * 8192, gsrc + tid * 16 + j * 8192);
            CP_COMMIT();
        }

        auto load_frags = [&](int k, int s) {
            const uint32_t kb = (uint32_t)(k * 32) + akb;
#pragma unroll
            for (int mt = 0; mt < 2; ++mt) {
                int r = arow + mt * 16;
                uint32_t off = (uint32_t)(r * 256) + (kb ^ (uint32_t)((r & 7) << 4));
                ldsm_x4(ah[s][mt], ahb + off);
            }
#pragma unroll
            for (int p = 0; p < 3; ++p) {
                int n = nb + p * 16 + (lane & 15);
                uint32_t off = (uint32_t)(n * 256) + (kb ^ (uint32_t)((n & 7) << 4));
                uint32_t t[4];
                ldsm_x4(t, sb + SM_BH + off);
                bh[s][2 * p][0] = t[0]; bh[s][2 * p][1] = t[2];
                bh[s][2 * p + 1][0] = t[1]; bh[s][2 * p + 1][1] = t[3];
            }
            {
                int n = nb + 48 + (lane & 7);
                uint32_t kb2 = (uint32_t)(k * 32) + (uint32_t)(((lane >> 3) & 1) << 4);
                uint32_t off = (uint32_t)(n * 256) + (kb2 ^ (uint32_t)((n & 7) << 4));
                uint32_t t[2];
                ldsm_x2(t, sb + SM_BH + off);
                bh[s][6][0] = t[0]; bh[s][6][1] = t[1];
            }
        };
        auto mma_block = [&](int s) {
#pragma unroll
            for (int mt = 0; mt < 2; ++mt)
#pragma unroll
                for (int nt = 0; nt < 7; ++nt) MMA_FP16(acc[mt][nt], ah[s][mt], bh[s][nt]);
        };

        // ---- 8 k-steps, 2-deep frag pipeline ----
        load_frags(0, 0);
#pragma unroll
        for (int k = 0; k < 8; ++k) {
            if (k < 7) load_frags(k + 1, (k + 1) & 1);
            mma_block(k & 1);
        }
    }

    // ---- epilogue ----
    const int h = h0 + warp_n;
    const int col0 = (lane & 3) * 2;
    const int r0 = lane >> 2;
#pragma unroll
    for (int mt = 0; mt < 2; ++mt) {
        int ocb = oct * 128 + warp_m * 32 + mt * 16;
        float* __restrict__ o0 = out + ((size_t)b * NOC + ocb + r0) * HW2 + (size_t)h * NHW;
        float* __restrict__ o1 = o0 + (size_t)8 * HW2;
#pragma unroll
        for (int nt = 0; nt < 7; ++nt) {
            int w = nt * 8 + col0;
            *(float2*)(o0 + w) = make_float2(acc[mt][nt][0], acc[mt][nt][1]);
            *(float2*)(o1 + w) = make_float2(acc[mt][nt][2], acc[mt][nt][3]);
        }
    }
}

// ---------------------------------------------------------------------------
extern "C" void kernel_launch(void* const* d_in, const int* in_sizes, int n_in,
                              void* d_out, int out_size) {
    const float* x     = nullptr;
    const int*   label = nullptr;
    const float* base  = nullptr;
    const float* mask  = nullptr;
    for (int i = 0; i < n_in; ++i) {
        switch (in_sizes[i]) {
            case 25690112: x     = (const float*)d_in[i]; break;
            case 64:       label = (const int*)  d_in[i]; break;
            case 294912:   base  = (const float*)d_in[i]; break;
            case 4608:     mask  = (const float*)d_in[i]; break;
            default: break;
        }
    }
    if (!x     && n_in > 0) x     = (const float*)d_in[0];
    if (!label && n_in > 1) label = (const int*)  d_in[1];
    if (!base  && n_in > 2) base  = (const float*)d_in[2];
    if (!mask  && n_in > 3) mask  = (const float*)d_in[3];

    float* out = (float*)d_out;

    {
        const int total = NDG * 2 * 9 * 128 * 128;
        prep_weights_kernel<<<(total + 255) / 256, 256>>>(base, mask);
    }
    cudaFuncSetAttribute(adaconv_mma_kernel,
                         cudaFuncAttributeMaxDynamicSharedMemorySize, SMEM_TOTAL);
    {
        dim3 grid(14, 2, NB);
        adaconv_mma_kernel<<<grid, NTHREADS, SMEM_TOTAL>>>(x, label, out);
    }
}

// round 11
// speedup vs baseline: 10.9638x; 1.5945x over previous
#include <cuda_runtime.h>
#include <cuda_fp16.h>
#include <cstdint>
#include <cstddef>

#define NB   64
#define NIC  128
#define NOC  256
#define NHW  56
#define NDG  4
#define HW2  (NHW*NHW)

#define NTHREADS 256
#define BROWS 232                  // (2 out rows + 2 halo) x 58 w-positions

// ---------------- smem layout (dynamic, 90 KB -> 2 CTAs/SM) ----------------
#define SM_BH   0                  // 232 * 256 B = 59392
#define SM_A    59392              // 32 KB single-buffered A tap
#define SMEM_TOTAL 92160

// Pre-swizzled fp16 weights: per (d, octile, tap): 16384 halfs (32 KB)
__device__ __align__(16) __half g_w2[NDG * 2 * 9 * 16384];

// ---------------- ptx helpers (baseline ISA only) ----------------
__device__ __forceinline__ uint32_t smem_u32(const void* p) {
    uint32_t a;
    asm("{ .reg .u64 t; cvta.to.shared.u64 t, %1; cvt.u32.u64 %0, t; }"
        : "=r"(a) : "l"(p));
    return a;
}
__device__ __forceinline__ void ldsm_x4(uint32_t* r, uint32_t addr) {
    asm volatile("ldmatrix.sync.aligned.m8n8.x4.shared.b16 {%0,%1,%2,%3}, [%4];"
                 : "=r"(r[0]), "=r"(r[1]), "=r"(r[2]), "=r"(r[3]) : "r"(addr));
}
__device__ __forceinline__ void ldsm_x2(uint32_t* r, uint32_t addr) {
    asm volatile("ldmatrix.sync.aligned.m8n8.x2.shared.b16 {%0,%1}, [%2];"
                 : "=r"(r[0]), "=r"(r[1]) : "r"(addr));
}
__device__ __forceinline__ void cp_async16(uint32_t saddr, const void* gptr) {
    asm volatile("cp.async.cg.shared.global [%0], [%1], 16;"
                 :: "r"(saddr), "l"(gptr) : "memory");
}
#define CP_COMMIT() asm volatile("cp.async.commit_group;" ::: "memory")
#define CP_WAIT0()  asm volatile("cp.async.wait_group 0;" ::: "memory")

#define MMA_FP16(c, a, b)                                                     \
    asm volatile(                                                             \
        "mma.sync.aligned.m16n8k16.row.col.f32.f16.f16.f32 "                  \
        "{%0,%1,%2,%3},{%4,%5,%6,%7},{%8,%9},{%0,%1,%2,%3};"                  \
        : "+f"((c)[0]), "+f"((c)[1]), "+f"((c)[2]), "+f"((c)[3])              \
        : "r"((a)[0]), "r"((a)[1]), "r"((a)[2]), "r"((a)[3]),                 \
          "r"((b)[0]), "r"((b)[1]))

// ---------------------------------------------------------------------------
// Prep: masked weights -> fp16, XOR-swizzled smem image
// ---------------------------------------------------------------------------
__global__ void prep_weights_kernel(const float* __restrict__ base,
                                    const float* __restrict__ mask) {
    int e = blockIdx.x * blockDim.x + threadIdx.x;
    const int total = NDG * 2 * 9 * 128 * 128;
    if (e >= total) return;
    int ic  = e % 128;
    int t2  = e / 128;
    int oc  = t2 % 128;
    int t3  = t2 / 128;
    int tap = t3 % 9;
    int t4  = t3 / 9;
    int oct = t4 % 2;
    int d   = t4 / 2;

    float w = base[((size_t)(oct * 128 + oc) * 128 + ic) * 9 + tap] *
              mask[((size_t)d * 128 + ic) * 9 + tap];

    uint32_t byte = (uint32_t)(oc * 256 + ((ic * 2) ^ ((oc & 7) << 4)));
    size_t slab = (size_t)((d * 2 + oct) * 9 + tap) * 16384;
    g_w2[slab + (byte >> 1)] = __float2half(w);
}

// ---------------------------------------------------------------------------
// CTA = (row-pair hp, octile 128, b). 256 threads = 8 warps: 4 M-warps
// (32 oc) x 2 N-warps (1 output row, N=56). Single-pass fp16, 2 CTAs/SM.
// ---------------------------------------------------------------------------
__global__ __launch_bounds__(NTHREADS, 2)
void adaconv_mma_kernel(const float* __restrict__ x,
                        const int*   __restrict__ label,
                        float*       __restrict__ out) {
    extern __shared__ char smem[];
    const uint32_t sb = smem_u32(smem);

    const int tid  = threadIdx.x;
    const int wid  = tid >> 5;
    const int lane = tid & 31;
    const int warp_m = wid & 3;       // oc tile of 32
    const int warp_n = wid >> 2;      // output row (0/1)

    const int hp  = blockIdx.x;       // 0..27
    const int oct = blockIdx.y;       // 0..1
    const int b   = blockIdx.z;       // 0..63
    const int h0  = hp * 2;

    int d = label[b];
    d = (d < 0) ? 0 : (d > NDG - 1 ? NDG - 1 : d);

    const float* __restrict__ xg = x + (size_t)b * NIC * HW2;
    const char* __restrict__ wbase =
        (const char*)(g_w2 + (size_t)((d * 2 + oct) * 9) * 16384);

    // ---- prologue: A(0) prefetch (2048 x 16B / 256 threads) ----
    {
#pragma unroll
        for (int j = 0; j < 8; ++j)
            cp_async16(sb + SM_A + tid * 16 + j * 4096, wbase + tid * 16 + j * 4096);
        CP_COMMIT();
    }

    // ---- build B once: thread tid owns n-row np=tid (<232), iterates ic ----
    if (tid < BROWS) {
        const int np   = tid;
        const int rowl = np / 58;            // one div per thread
        const int wq   = np - rowl * 58;
        const int h_in = h0 - 1 + rowl;
        const int w_in = wq - 1;
        const bool inb = (h_in >= 0 && h_in < NHW && w_in >= 0 && w_in < NHW);
        const float* __restrict__ xp = xg + (size_t)h_in * NHW + w_in;
        const uint32_t brow = (uint32_t)(np * 256);
        const uint32_t bx   = (uint32_t)((np & 7) << 4);
#pragma unroll 8
        for (int icp = 0; icp < 64; ++icp) {
            float v0 = 0.f, v1 = 0.f;
            if (inb) {
                v0 = xp[(size_t)(icp * 2) * HW2];
                v1 = xp[(size_t)(icp * 2 + 1) * HW2];
            }
            __half h0b = __float2half(v0);
            __half h1b = __float2half(v1);
            uint32_t hw = (uint32_t)__half_as_ushort(h0b) |
                          ((uint32_t)__half_as_ushort(h1b) << 16);
            uint32_t byte = brow + (((uint32_t)(icp * 4)) ^ bx);
            *(uint32_t*)(smem + SM_BH + byte) = hw;
        }
    }

    float acc[2][7][4];
#pragma unroll
    for (int mt = 0; mt < 2; ++mt)
#pragma unroll
        for (int nt = 0; nt < 7; ++nt)
#pragma unroll
            for (int q = 0; q < 4; ++q) acc[mt][nt][q] = 0.f;

    const int arow     = warp_m * 32 + (lane & 15);
    const uint32_t akb = (uint32_t)((lane >> 4) << 4);
    const uint32_t ab  = sb + SM_A;

    uint32_t ah[2][2][4], bh[2][7][2];

    for (int tap = 0; tap < 9; ++tap) {
        const int dh = tap / 3, dw = tap % 3;
        const int nb = (warp_n + dh) * 58 + dw;

        CP_WAIT0();
        __syncthreads();   // A(tap) visible (+ B on tap 0)

        auto load_frags = [&](int k, int s) {
            const uint32_t kb = (uint32_t)(k * 32) + akb;
#pragma unroll
            for (int mt = 0; mt < 2; ++mt) {
                int r = arow + mt * 16;
                uint32_t off = (uint32_t)(r * 256) + (kb ^ (uint32_t)((r & 7) << 4));
                ldsm_x4(ah[s][mt], ab + off);
            }
#pragma unroll
            for (int p = 0; p < 3; ++p) {
                int n = nb + p * 16 + (lane & 15);
                uint32_t off = (uint32_t)(n * 256) + (kb ^ (uint32_t)((n & 7) << 4));
                uint32_t t[4];
                ldsm_x4(t, sb + SM_BH + off);
                bh[s][2 * p][0] = t[0]; bh[s][2 * p][1] = t[2];
                bh[s][2 * p + 1][0] = t[1]; bh[s][2 * p + 1][1] = t[3];
            }
            {
                int n = nb + 48 + (lane & 7);
                uint32_t kb2 = (uint32_t)(k * 32) + (uint32_t)(((lane >> 3) & 1) << 4);
                uint32_t off = (uint32_t)(n * 256) + (kb2 ^ (uint32_t)((n & 7) << 4));
                uint32_t t[2];
                ldsm_x2(t, sb + SM_BH + off);
                bh[s][6][0] = t[0]; bh[s][6][1] = t[1];
            }
        };
        auto mma_block = [&](int s) {
#pragma unroll
            for (int mt = 0; mt < 2; ++mt)
#pragma unroll
                for (int nt = 0; nt < 7; ++nt) MMA_FP16(acc[mt][nt], ah[s][mt], bh[s][nt]);
        };

        // ---- 8 k-steps, 2-deep frag pipeline ----
        load_frags(0, 0);
#pragma unroll
        for (int k = 0; k < 8; ++k) {
            if (k < 7) load_frags(k + 1, (k + 1) & 1);
            mma_block(k & 1);
        }

        __syncthreads();   // all warps done reading A(tap)
        if (tap < 8) {     // refill single A buffer for next tap
            const char* gsrc = wbase + (size_t)(tap + 1) * 32768;
#pragma unroll
            for (int j = 0; j < 8; ++j)
                cp_async16(sb + SM_A + tid * 16 + j * 4096, gsrc + tid * 16 + j * 4096);
            CP_COMMIT();
        }
    }

    // ---- epilogue ----
    const int h = h0 + warp_n;
    const int col0 = (lane & 3) * 2;
    const int r0 = lane >> 2;
#pragma unroll
    for (int mt = 0; mt < 2; ++mt) {
        int ocb = oct * 128 + warp_m * 32 + mt * 16;
        float* __restrict__ o0 = out + ((size_t)b * NOC + ocb + r0) * HW2 + (size_t)h * NHW;
        float* __restrict__ o1 = o0 + (size_t)8 * HW2;
#pragma unroll
        for (int nt = 0; nt < 7; ++nt) {
            int w = nt * 8 + col0;
            *(float2*)(o0 + w) = make_float2(acc[mt][nt][0], acc[mt][nt][1]);
            *(float2*)(o1 + w) = make_float2(acc[mt][nt][2], acc[mt][nt][3]);
        }
    }
}

// ---------------------------------------------------------------------------
extern "C" void kernel_launch(void* const* d_in, const int* in_sizes, int n_in,
                              void* d_out, int out_size) {
    const float* x     = nullptr;
    const int*   label = nullptr;
    const float* base  = nullptr;
    const float* mask  = nullptr;
    for (int i = 0; i < n_in; ++i) {
        switch (in_sizes[i]) {
            case 25690112: x     = (const float*)d_in[i]; break;
            case 64:       label = (const int*)  d_in[i]; break;
            case 294912:   base  = (const float*)d_in[i]; break;
            case 4608:     mask  = (const float*)d_in[i]; break;
            default: break;
        }
    }
    if (!x     && n_in > 0) x     = (const float*)d_in[0];
    if (!label && n_in > 1) label = (const int*)  d_in[1];
    if (!base  && n_in > 2) base  = (const float*)d_in[2];
    if (!mask  && n_in > 3) mask  = (const float*)d_in[3];

    float* out = (float*)d_out;

    {
        const int total = NDG * 2 * 9 * 128 * 128;
        prep_weights_kernel<<<(total + 255) / 256, 256>>>(base, mask);
    }
    cudaFuncSetAttribute(adaconv_mma_kernel,
                         cudaFuncAttributeMaxDynamicSharedMemorySize, SMEM_TOTAL);
    {
        dim3 grid(28, 2, NB);
        adaconv_mma_kernel<<<grid, NTHREADS, SMEM_TOTAL>>>(x, label, out);
    }
}